// round 11
// baseline (speedup 1.0000x reference)
#include <cuda_runtime.h>

#define Bb   2
#define Ss   1024
#define Hh   768
#define Dd   24
#define Kk   96
#define VIN  2304
#define VHID 768

// ---------------- scratch ----------------
__device__ float g_Zj[Bb * Ss * Dd];
__device__ float g_Zi[Bb * Ss * Dd];
__device__ float g_CJ[Bb * Ss * Kk];
__device__ float g_CI[Bb * Ss * Kk];
__device__ float g_probs[(size_t)Bb * Ss * Ss];
__device__ float g_ctx[Bb * Ss * Hh];
__device__ float g_ctxh[Bb * Ss * Hh];
__device__ float g_hid[Bb * Ss * VHID];

__device__ __forceinline__ unsigned tf32r(float x) {
    unsigned r;
    asm("cvt.rna.tf32.f32 %0, %1;" : "=r"(r) : "f"(x));
    return r;
}
__device__ __forceinline__ void mma_tf32(float& d0, float& d1, float& d2, float& d3,
                                         unsigned a0, unsigned a1, unsigned a2, unsigned a3,
                                         unsigned b0, unsigned b1) {
    asm volatile(
        "mma.sync.aligned.m16n8k8.row.col.f32.tf32.tf32.f32 "
        "{%0,%1,%2,%3}, {%4,%5,%6,%7}, {%8,%9}, {%0,%1,%2,%3};"
        : "+f"(d0), "+f"(d1), "+f"(d2), "+f"(d3)
        : "r"(a0), "r"(a1), "r"(a2), "r"(a3), "r"(b0), "r"(b1));
}

// ================= K1: Zj, Zi, cj = b1 + Zj@W1a, ci = Zi@W1b =================
__global__ __launch_bounds__(128) void k1_prep(const float* __restrict__ Hj,
                                               const float* __restrict__ Hi,
                                               const float* __restrict__ Wpj,
                                               const float* __restrict__ Wpi,
                                               const float* __restrict__ W1,
                                               const float* __restrict__ b1) {
    int bs  = blockIdx.x;
    int tid = threadIdx.x;
    int w   = tid >> 5, l = tid & 31;
    __shared__ float part[4][Dd];
    __shared__ float zjs[Dd], zis[Dd];

    const float* Hrow = (w < 2 ? Hj : Hi) + (size_t)bs * Hh;
    const float* Wp   = (w < 2 ? Wpj : Wpi);
    if (l < Dd) {
        float acc = 0.f;
        int h0 = (w & 1) * (Hh / 2);
#pragma unroll 4
        for (int h = h0; h < h0 + Hh / 2; ++h)
            acc = fmaf(Hrow[h], Wp[h * Dd + l], acc);
        part[w][l] = acc;
    }
    __syncthreads();
    if (tid < Dd) {
        float z = part[0][tid] + part[1][tid];
        zjs[tid] = z;
        g_Zj[bs * Dd + tid] = z;
    }
    if (tid >= 32 && tid < 32 + Dd) {
        int d = tid - 32;
        float z = part[2][d] + part[3][d];
        zis[d] = z;
        g_Zi[bs * Dd + d] = z;
    }
    __syncthreads();
    if (tid < Kk) {
        float cj = b1[tid], ci = 0.f;
#pragma unroll
        for (int d = 0; d < Dd; ++d) {
            cj = fmaf(zjs[d], W1[d * Kk + tid], cj);
            ci = fmaf(zis[d], W1[(Dd + d) * Kk + tid], ci);
        }
        g_CJ[bs * Kk + tid] = cj;
        g_CI[bs * Kk + tid] = ci;
    }
}

// ================= K2 (tensor-core, R10 measured-best, unchanged) =================
__global__ __launch_bounds__(256) void k2_mma(const float* __restrict__ W1,
                                              const float* __restrict__ W2,
                                              const float* __restrict__ mask) {
    const int bs  = blockIdx.x;
    const int b   = bs >> 10;
    const int tid = threadIdx.x;
    const int warp = tid >> 5, lane = tid & 31;
    const int g  = lane >> 2, t4 = lane & 3;
    const int wm = warp & 1;   // m offset wm*32
    const int wn = warp >> 1;  // n offset wn*24

    __shared__ unsigned Ws[48][104];
    __shared__ unsigned Fs[64][52];
    __shared__ float cjw[Kk], w2s[Kk], zjs[Dd];
    __shared__ float lg[Ss];
    __shared__ float lgpart[4][64];
    __shared__ float red[8];

    for (int idx = tid; idx < 48 * Kk; idx += 256) {
        int d = idx / Kk, k = idx - d * Kk;
        float v = (d < Dd) ? W1[(2 * Dd + d) * Kk + k] : W1[(3 * Dd + (d - Dd)) * Kk + k];
        Ws[d][k] = tf32r(v);
    }
    if (tid < Kk) {
        cjw[tid] = g_CJ[(size_t)bs * Kk + tid];
        w2s[tid] = W2[tid];
    }
    if (tid < Dd) zjs[tid] = g_Zj[(size_t)bs * Dd + tid];
    __syncthreads();

    float zj[Dd];
#pragma unroll
    for (int d = 0; d < Dd; ++d) zj[d] = zjs[d];

    const float* ciBase = g_CI + (size_t)b * Ss * Kk;
    const float* ziBase = g_Zi + (size_t)b * Ss * Dd;

#pragma unroll 1
    for (int sub = 0; sub < 16; ++sub) {
        const int t0 = sub * 64;

        {
            const int r = tid >> 2, p = tid & 3;
            const int t = t0 + r;
            const int half = p & 1;
            const float* zr = ziBase + (size_t)t * Dd + half * 12;
            float zi[12];
#pragma unroll
            for (int q = 0; q < 3; ++q) {
                float4 v = *(const float4*)(zr + 4 * q);
                zi[4 * q] = v.x; zi[4 * q + 1] = v.y; zi[4 * q + 2] = v.z; zi[4 * q + 3] = v.w;
            }
            const int base = half * 12 + ((p >= 2) ? 24 : 0);
            if (p < 2) {
#pragma unroll
                for (int j = 0; j < 12; ++j)
                    Fs[r][base + j] = tf32r(zj[half * 12 + j] * zi[j]);
            } else {
#pragma unroll
                for (int j = 0; j < 12; ++j)
                    Fs[r][base + j] = tf32r(fabsf(zj[half * 12 + j] - zi[j]));
            }
        }
        __syncthreads();

        float acc[2][3][4];
#pragma unroll
        for (int mt = 0; mt < 2; ++mt) {
            int r0 = wm * 32 + mt * 16 + g;
            int r1 = r0 + 8;
#pragma unroll
            for (int nt = 0; nt < 3; ++nt) {
                int c = wn * 24 + nt * 8 + 2 * t4;
                float2 ci0 = *(const float2*)(ciBase + (size_t)(t0 + r0) * Kk + c);
                float2 ci1 = *(const float2*)(ciBase + (size_t)(t0 + r1) * Kk + c);
                acc[mt][nt][0] = ci0.x + cjw[c];
                acc[mt][nt][1] = ci0.y + cjw[c + 1];
                acc[mt][nt][2] = ci1.x + cjw[c];
                acc[mt][nt][3] = ci1.y + cjw[c + 1];
            }
        }

#pragma unroll
        for (int k8 = 0; k8 < 48; k8 += 8) {
            unsigned afr[2][4], bfr[3][2];
#pragma unroll
            for (int mt = 0; mt < 2; ++mt) {
                int rb = wm * 32 + mt * 16 + g;
                afr[mt][0] = Fs[rb][k8 + t4];
                afr[mt][1] = Fs[rb + 8][k8 + t4];
                afr[mt][2] = Fs[rb][k8 + t4 + 4];
                afr[mt][3] = Fs[rb + 8][k8 + t4 + 4];
            }
#pragma unroll
            for (int nt = 0; nt < 3; ++nt) {
                int cb = wn * 24 + nt * 8 + g;
                bfr[nt][0] = Ws[k8 + t4][cb];
                bfr[nt][1] = Ws[k8 + t4 + 4][cb];
            }
#pragma unroll
            for (int mt = 0; mt < 2; ++mt)
#pragma unroll
                for (int nt = 0; nt < 3; ++nt)
                    mma_tf32(acc[mt][nt][0], acc[mt][nt][1], acc[mt][nt][2], acc[mt][nt][3],
                             afr[mt][0], afr[mt][1], afr[mt][2], afr[mt][3],
                             bfr[nt][0], bfr[nt][1]);
        }

#pragma unroll
        for (int mt = 0; mt < 2; ++mt) {
            float p0 = 0.f, p1 = 0.f;
#pragma unroll
            for (int nt = 0; nt < 3; ++nt) {
                int c = wn * 24 + nt * 8 + 2 * t4;
                float wa = w2s[c], wb = w2s[c + 1];
                p0 = fmaf(fmaxf(acc[mt][nt][0], 0.f), wa, p0);
                p0 = fmaf(fmaxf(acc[mt][nt][1], 0.f), wb, p0);
                p1 = fmaf(fmaxf(acc[mt][nt][2], 0.f), wa, p1);
                p1 = fmaf(fmaxf(acc[mt][nt][3], 0.f), wb, p1);
            }
            p0 += __shfl_xor_sync(0xffffffffu, p0, 1);
            p0 += __shfl_xor_sync(0xffffffffu, p0, 2);
            p1 += __shfl_xor_sync(0xffffffffu, p1, 1);
            p1 += __shfl_xor_sync(0xffffffffu, p1, 2);
            if (t4 == 0) {
                lgpart[wn][wm * 32 + mt * 16 + g]     = p0;
                lgpart[wn][wm * 32 + mt * 16 + g + 8] = p1;
            }
        }
        __syncthreads();
        if (tid < 64) {
            float v = (lgpart[0][tid] + lgpart[1][tid]) + (lgpart[2][tid] + lgpart[3][tid]);
            int t = t0 + tid;
            float m = mask[b * Ss + t];
            lg[t] = v + (1.0f - m) * (-3.402823466e38f);
        }
        __syncthreads();
    }

    float mx = -3.402823466e38f;
    for (int i = tid; i < Ss; i += 256) mx = fmaxf(mx, lg[i]);
#pragma unroll
    for (int o = 16; o; o >>= 1) mx = fmaxf(mx, __shfl_xor_sync(0xffffffffu, mx, o));
    if (lane == 0) red[warp] = mx;
    __syncthreads();
    mx = red[0];
#pragma unroll
    for (int w2i = 1; w2i < 8; ++w2i) mx = fmaxf(mx, red[w2i]);
    __syncthreads();

    float sum = 0.f;
    for (int i = tid; i < Ss; i += 256) {
        float e = __expf(lg[i] - mx);
        lg[i] = e;
        sum += e;
    }
#pragma unroll
    for (int o = 16; o; o >>= 1) sum += __shfl_xor_sync(0xffffffffu, sum, o);
    if (lane == 0) red[warp] = sum;
    __syncthreads();
    sum = 0.f;
#pragma unroll
    for (int w2i = 0; w2i < 8; ++w2i) sum += red[w2i];
    float inv = 1.0f / sum;

    float* orow = g_probs + (size_t)bs * Ss;
    for (int i = tid; i < Ss; i += 256) orow[i] = lg[i] * inv;
}

// ====== tf32 GEMM: 128x48 tile (256 blocks -> 2 resident/SM), 256 thr, k-slab 16 ======
// warps: wm = warp&3 (4 x 32 rows), wn = warp>>2 (2 x 24 cols); per warp 2 mt x 3 nt.
// MODE 0: ctx = probs @ H_i (per b); epilogue also writes ctxh = ctx * Hj
// MODE 1: hid = relu([ctx|Hj|ctxh] @ Wv1 + bv1)
// MODE 2: out = alpha * (hid @ Wv2 + bv2)
template <int MODE>
__global__ __launch_bounds__(256) void gemm_mma(const float* __restrict__ Ap,
                                                const float* __restrict__ Bp,
                                                const float* __restrict__ Hjp,
                                                const float* __restrict__ bias,
                                                const float* __restrict__ alpha,
                                                float* __restrict__ Cp, int Kdim, int lda) {
    const int m0 = blockIdx.x * 128;
    const int n0 = blockIdx.y * 48;
    const float* A = Ap;
    const float* Bm = Bp;
    float* C = Cp;
    size_t rowbase = 0;
    if (MODE == 0) {
        int b = blockIdx.z;
        A += (size_t)b * Ss * Ss;
        Bm += (size_t)b * Ss * Hh;
        C += (size_t)b * Ss * Hh;
        rowbase = (size_t)b * Ss;
    }

    // pad 20: A-frag (20*g + t4) mod 32 distinct -> conflict-free
    __shared__ unsigned As[2][128][20];   // 20.5 KB
    // pad 56: B-frag (56*t4 + g) mod 32 = {0,24,16,8}+{0..7} distinct -> conflict-free
    __shared__ unsigned Bs[2][16][56];    // 7.2 KB

    const int tid  = threadIdx.x;
    const int warp = tid >> 5, lane = tid & 31;
    const int g  = lane >> 2, t4 = lane & 3;
    const int wm = warp & 3;   // m offset wm*32
    const int wn = warp >> 2;  // n offset wn*24

    // A global load: row = tid>>1, k-offset = (tid&1)*8 (two float4)
    const int ar = tid >> 1, ac = (tid & 1) * 8;
    // B global load: 16 x 48 floats = 192 float4, threads 0..191
    const bool bload = (tid < 192);
    const int b0r = tid / 12, b0c = (tid % 12) * 4;

    float acc[2][3][4];
#pragma unroll
    for (int mt = 0; mt < 2; ++mt)
#pragma unroll
        for (int nt = 0; nt < 3; ++nt)
#pragma unroll
            for (int v = 0; v < 4; ++v) acc[mt][nt][v] = 0.f;

    const int nkt = Kdim / 16;

    float4 pa0, pa1, pb0;

    auto loadAB = [&](int k0) {
        int kc = k0 + ac;
        if (MODE == 1) {
            int seg = kc / Hh;  // slab-uniform (Hh % 16 == 0)
            const float* base = (seg == 0) ? g_ctx : (seg == 1) ? Hjp : g_ctxh;
            int kq = kc - seg * Hh;
            pa0 = *(const float4*)(base + (size_t)(m0 + ar) * Hh + kq);
            pa1 = *(const float4*)(base + (size_t)(m0 + ar) * Hh + kq + 4);
        } else {
            pa0 = *(const float4*)(A + (size_t)(m0 + ar) * lda + kc);
            pa1 = *(const float4*)(A + (size_t)(m0 + ar) * lda + kc + 4);
        }
        if (bload) pb0 = *(const float4*)(Bm + (size_t)(k0 + b0r) * Hh + n0 + b0c);
    };

    auto storeAB = [&](int buf) {
        const float va[8] = {pa0.x, pa0.y, pa0.z, pa0.w, pa1.x, pa1.y, pa1.z, pa1.w};
#pragma unroll
        for (int j = 0; j < 8; ++j) As[buf][ar][ac + j] = tf32r(va[j]);
        if (bload) {
            const float w0[4] = {pb0.x, pb0.y, pb0.z, pb0.w};
#pragma unroll
            for (int j = 0; j < 4; ++j) Bs[buf][b0r][b0c + j] = tf32r(w0[j]);
        }
    };

    loadAB(0);
    storeAB(0);
    __syncthreads();

#pragma unroll 1
    for (int kt = 0; kt < nkt; ++kt) {
        const int cur = kt & 1;
        const bool more = (kt + 1 < nkt);
        if (more) loadAB((kt + 1) * 16);

#pragma unroll
        for (int k8 = 0; k8 < 16; k8 += 8) {
            unsigned afr[2][4], bfr[3][2];
#pragma unroll
            for (int mt = 0; mt < 2; ++mt) {
                int rb = wm * 32 + mt * 16 + g;
                afr[mt][0] = As[cur][rb][k8 + t4];
                afr[mt][1] = As[cur][rb + 8][k8 + t4];
                afr[mt][2] = As[cur][rb][k8 + t4 + 4];
                afr[mt][3] = As[cur][rb + 8][k8 + t4 + 4];
            }
#pragma unroll
            for (int nt = 0; nt < 3; ++nt) {
                int cb = wn * 24 + nt * 8 + g;
                bfr[nt][0] = Bs[cur][k8 + t4][cb];
                bfr[nt][1] = Bs[cur][k8 + t4 + 4][cb];
            }
#pragma unroll
            for (int mt = 0; mt < 2; ++mt)
#pragma unroll
                for (int nt = 0; nt < 3; ++nt)
                    mma_tf32(acc[mt][nt][0], acc[mt][nt][1], acc[mt][nt][2], acc[mt][nt][3],
                             afr[mt][0], afr[mt][1], afr[mt][2], afr[mt][3],
                             bfr[nt][0], bfr[nt][1]);
        }
        if (more) {
            storeAB(cur ^ 1);   // buffer last read before previous sync
            __syncthreads();
        }
    }

    // ---------------- epilogue ----------------
    const float al = (MODE == 2) ? alpha[0] : 0.f;
#pragma unroll
    for (int mt = 0; mt < 2; ++mt) {
        int r0 = m0 + wm * 32 + mt * 16 + g;
        int r1 = r0 + 8;
#pragma unroll
        for (int nt = 0; nt < 3; ++nt) {
            int c0 = n0 + wn * 24 + nt * 8 + 2 * t4;  // even -> 8B aligned
            float v00 = acc[mt][nt][0], v01 = acc[mt][nt][1];
            float v10 = acc[mt][nt][2], v11 = acc[mt][nt][3];
            if (MODE == 0) {
                *(float2*)(&C[(size_t)r0 * Hh + c0]) = make_float2(v00, v01);
                *(float2*)(&C[(size_t)r1 * Hh + c0]) = make_float2(v10, v11);
                size_t g0 = rowbase + r0, g1 = rowbase + r1;
                float2 h0 = *(const float2*)(Hjp + g0 * Hh + c0);
                float2 h1 = *(const float2*)(Hjp + g1 * Hh + c0);
                *(float2*)(&g_ctxh[g0 * Hh + c0]) = make_float2(v00 * h0.x, v01 * h0.y);
                *(float2*)(&g_ctxh[g1 * Hh + c0]) = make_float2(v10 * h1.x, v11 * h1.y);
            } else if (MODE == 1) {
                float2 bsv = *(const float2*)(&bias[c0]);
                *(float2*)(&C[(size_t)r0 * VHID + c0]) =
                    make_float2(fmaxf(v00 + bsv.x, 0.f), fmaxf(v01 + bsv.y, 0.f));
                *(float2*)(&C[(size_t)r1 * VHID + c0]) =
                    make_float2(fmaxf(v10 + bsv.x, 0.f), fmaxf(v11 + bsv.y, 0.f));
            } else {
                float2 bsv = *(const float2*)(&bias[c0]);
                *(float2*)(&C[(size_t)r0 * Hh + c0]) =
                    make_float2(al * (v00 + bsv.x), al * (v01 + bsv.y));
                *(float2*)(&C[(size_t)r1 * Hh + c0]) =
                    make_float2(al * (v10 + bsv.x), al * (v11 + bsv.y));
            }
        }
    }
}

// ================= launch =================
extern "C" void kernel_launch(void* const* d_in, const int* in_sizes, int n_in, void* d_out,
                              int out_size) {
    const float* Hj   = (const float*)d_in[0];
    const float* Hi   = (const float*)d_in[1];
    const float* mask = (const float*)d_in[2];
    const float* Wpj  = (const float*)d_in[3];
    const float* Wpi  = (const float*)d_in[4];
    const float* W1   = (const float*)d_in[5];
    const float* b1   = (const float*)d_in[6];
    const float* W2   = (const float*)d_in[7];
    // d_in[8] = b2: constant logit shift -> cancels in softmax
    const float* Wv1   = (const float*)d_in[9];
    const float* bv1   = (const float*)d_in[10];
    const float* Wv2   = (const float*)d_in[11];
    const float* bv2   = (const float*)d_in[12];
    const float* alpha = (const float*)d_in[13];
    float* out = (float*)d_out;

    float* d_probs = nullptr;
    float* d_ctx = nullptr;
    float* d_hid = nullptr;
    cudaGetSymbolAddress((void**)&d_probs, g_probs);
    cudaGetSymbolAddress((void**)&d_ctx, g_ctx);
    cudaGetSymbolAddress((void**)&d_hid, g_hid);

    k1_prep<<<Bb * Ss, 128>>>(Hj, Hi, Wpj, Wpi, W1, b1);
    k2_mma<<<Bb * Ss, 256>>>(W1, W2, mask);
    gemm_mma<0><<<dim3(Ss / 128, Hh / 48, Bb), 256>>>(d_probs, Hi, Hj, nullptr, nullptr,
                                                      d_ctx, Ss, Ss);
    gemm_mma<1><<<dim3(Bb * Ss / 128, VHID / 48), 256>>>(nullptr, Wv1, Hj, bv1, nullptr, d_hid,
                                                         VIN, 0);
    gemm_mma<2><<<dim3(Bb * Ss / 128, Hh / 48), 256>>>(d_hid, Wv2, nullptr, bv2, alpha, out,
                                                       VHID, VHID);
}

// round 13
// speedup vs baseline: 1.1123x; 1.1123x over previous
#include <cuda_runtime.h>

#define Bb   2
#define Ss   1024
#define Hh   768
#define Dd   24
#define Kk   96
#define VIN  2304
#define VHID 768

// ---------------- scratch ----------------
__device__ float g_Zj[Bb * Ss * Dd];
__device__ float g_Zi[Bb * Ss * Dd];
__device__ float g_CJ[Bb * Ss * Kk];
__device__ float g_CI[Bb * Ss * Kk];
__device__ float g_probs[(size_t)Bb * Ss * Ss];
__device__ float g_ctx[Bb * Ss * Hh];
__device__ float g_ctxh[Bb * Ss * Hh];
__device__ float g_hid[Bb * Ss * VHID];

__device__ __forceinline__ unsigned tf32r(float x) {
    unsigned r;
    asm("cvt.rna.tf32.f32 %0, %1;" : "=r"(r) : "f"(x));
    return r;
}
__device__ __forceinline__ void mma_tf32(float& d0, float& d1, float& d2, float& d3,
                                         unsigned a0, unsigned a1, unsigned a2, unsigned a3,
                                         unsigned b0, unsigned b1) {
    asm volatile(
        "mma.sync.aligned.m16n8k8.row.col.f32.tf32.tf32.f32 "
        "{%0,%1,%2,%3}, {%4,%5,%6,%7}, {%8,%9}, {%0,%1,%2,%3};"
        : "+f"(d0), "+f"(d1), "+f"(d2), "+f"(d3)
        : "r"(a0), "r"(a1), "r"(a2), "r"(a3), "r"(b0), "r"(b1));
}

// ================= K1: Zj, Zi, cj = b1 + Zj@W1a, ci = Zi@W1b =================
__global__ __launch_bounds__(128) void k1_prep(const float* __restrict__ Hj,
                                               const float* __restrict__ Hi,
                                               const float* __restrict__ Wpj,
                                               const float* __restrict__ Wpi,
                                               const float* __restrict__ W1,
                                               const float* __restrict__ b1) {
    int bs  = blockIdx.x;
    int tid = threadIdx.x;
    int w   = tid >> 5, l = tid & 31;
    __shared__ float part[4][Dd];
    __shared__ float zjs[Dd], zis[Dd];

    const float* Hrow = (w < 2 ? Hj : Hi) + (size_t)bs * Hh;
    const float* Wp   = (w < 2 ? Wpj : Wpi);
    if (l < Dd) {
        float acc = 0.f;
        int h0 = (w & 1) * (Hh / 2);
#pragma unroll 4
        for (int h = h0; h < h0 + Hh / 2; ++h)
            acc = fmaf(Hrow[h], Wp[h * Dd + l], acc);
        part[w][l] = acc;
    }
    __syncthreads();
    if (tid < Dd) {
        float z = part[0][tid] + part[1][tid];
        zjs[tid] = z;
        g_Zj[bs * Dd + tid] = z;
    }
    if (tid >= 32 && tid < 32 + Dd) {
        int d = tid - 32;
        float z = part[2][d] + part[3][d];
        zis[d] = z;
        g_Zi[bs * Dd + d] = z;
    }
    __syncthreads();
    if (tid < Kk) {
        float cj = b1[tid], ci = 0.f;
#pragma unroll
        for (int d = 0; d < Dd; ++d) {
            cj = fmaf(zjs[d], W1[d * Kk + tid], cj);
            ci = fmaf(zis[d], W1[(Dd + d) * Kk + tid], ci);
        }
        g_CJ[bs * Kk + tid] = cj;
        g_CI[bs * Kk + tid] = ci;
    }
}

// ================= K2 (tensor-core, R10 measured-best, unchanged) =================
__global__ __launch_bounds__(256) void k2_mma(const float* __restrict__ W1,
                                              const float* __restrict__ W2,
                                              const float* __restrict__ mask) {
    const int bs  = blockIdx.x;
    const int b   = bs >> 10;
    const int tid = threadIdx.x;
    const int warp = tid >> 5, lane = tid & 31;
    const int g  = lane >> 2, t4 = lane & 3;
    const int wm = warp & 1;
    const int wn = warp >> 1;

    __shared__ unsigned Ws[48][104];
    __shared__ unsigned Fs[64][52];
    __shared__ float cjw[Kk], w2s[Kk], zjs[Dd];
    __shared__ float lg[Ss];
    __shared__ float lgpart[4][64];
    __shared__ float red[8];

    for (int idx = tid; idx < 48 * Kk; idx += 256) {
        int d = idx / Kk, k = idx - d * Kk;
        float v = (d < Dd) ? W1[(2 * Dd + d) * Kk + k] : W1[(3 * Dd + (d - Dd)) * Kk + k];
        Ws[d][k] = tf32r(v);
    }
    if (tid < Kk) {
        cjw[tid] = g_CJ[(size_t)bs * Kk + tid];
        w2s[tid] = W2[tid];
    }
    if (tid < Dd) zjs[tid] = g_Zj[(size_t)bs * Dd + tid];
    __syncthreads();

    float zj[Dd];
#pragma unroll
    for (int d = 0; d < Dd; ++d) zj[d] = zjs[d];

    const float* ciBase = g_CI + (size_t)b * Ss * Kk;
    const float* ziBase = g_Zi + (size_t)b * Ss * Dd;

#pragma unroll 1
    for (int sub = 0; sub < 16; ++sub) {
        const int t0 = sub * 64;

        {
            const int r = tid >> 2, p = tid & 3;
            const int t = t0 + r;
            const int half = p & 1;
            const float* zr = ziBase + (size_t)t * Dd + half * 12;
            float zi[12];
#pragma unroll
            for (int q = 0; q < 3; ++q) {
                float4 v = *(const float4*)(zr + 4 * q);
                zi[4 * q] = v.x; zi[4 * q + 1] = v.y; zi[4 * q + 2] = v.z; zi[4 * q + 3] = v.w;
            }
            const int base = half * 12 + ((p >= 2) ? 24 : 0);
            if (p < 2) {
#pragma unroll
                for (int j = 0; j < 12; ++j)
                    Fs[r][base + j] = tf32r(zj[half * 12 + j] * zi[j]);
            } else {
#pragma unroll
                for (int j = 0; j < 12; ++j)
                    Fs[r][base + j] = tf32r(fabsf(zj[half * 12 + j] - zi[j]));
            }
        }
        __syncthreads();

        float acc[2][3][4];
#pragma unroll
        for (int mt = 0; mt < 2; ++mt) {
            int r0 = wm * 32 + mt * 16 + g;
            int r1 = r0 + 8;
#pragma unroll
            for (int nt = 0; nt < 3; ++nt) {
                int c = wn * 24 + nt * 8 + 2 * t4;
                float2 ci0 = *(const float2*)(ciBase + (size_t)(t0 + r0) * Kk + c);
                float2 ci1 = *(const float2*)(ciBase + (size_t)(t0 + r1) * Kk + c);
                acc[mt][nt][0] = ci0.x + cjw[c];
                acc[mt][nt][1] = ci0.y + cjw[c + 1];
                acc[mt][nt][2] = ci1.x + cjw[c];
                acc[mt][nt][3] = ci1.y + cjw[c + 1];
            }
        }

#pragma unroll
        for (int k8 = 0; k8 < 48; k8 += 8) {
            unsigned afr[2][4], bfr[3][2];
#pragma unroll
            for (int mt = 0; mt < 2; ++mt) {
                int rb = wm * 32 + mt * 16 + g;
                afr[mt][0] = Fs[rb][k8 + t4];
                afr[mt][1] = Fs[rb + 8][k8 + t4];
                afr[mt][2] = Fs[rb][k8 + t4 + 4];
                afr[mt][3] = Fs[rb + 8][k8 + t4 + 4];
            }
#pragma unroll
            for (int nt = 0; nt < 3; ++nt) {
                int cb = wn * 24 + nt * 8 + g;
                bfr[nt][0] = Ws[k8 + t4][cb];
                bfr[nt][1] = Ws[k8 + t4 + 4][cb];
            }
#pragma unroll
            for (int mt = 0; mt < 2; ++mt)
#pragma unroll
                for (int nt = 0; nt < 3; ++nt)
                    mma_tf32(acc[mt][nt][0], acc[mt][nt][1], acc[mt][nt][2], acc[mt][nt][3],
                             afr[mt][0], afr[mt][1], afr[mt][2], afr[mt][3],
                             bfr[nt][0], bfr[nt][1]);
        }

#pragma unroll
        for (int mt = 0; mt < 2; ++mt) {
            float p0 = 0.f, p1 = 0.f;
#pragma unroll
            for (int nt = 0; nt < 3; ++nt) {
                int c = wn * 24 + nt * 8 + 2 * t4;
                float wa = w2s[c], wb = w2s[c + 1];
                p0 = fmaf(fmaxf(acc[mt][nt][0], 0.f), wa, p0);
                p0 = fmaf(fmaxf(acc[mt][nt][1], 0.f), wb, p0);
                p1 = fmaf(fmaxf(acc[mt][nt][2], 0.f), wa, p1);
                p1 = fmaf(fmaxf(acc[mt][nt][3], 0.f), wb, p1);
            }
            p0 += __shfl_xor_sync(0xffffffffu, p0, 1);
            p0 += __shfl_xor_sync(0xffffffffu, p0, 2);
            p1 += __shfl_xor_sync(0xffffffffu, p1, 1);
            p1 += __shfl_xor_sync(0xffffffffu, p1, 2);
            if (t4 == 0) {
                lgpart[wn][wm * 32 + mt * 16 + g]     = p0;
                lgpart[wn][wm * 32 + mt * 16 + g + 8] = p1;
            }
        }
        __syncthreads();
        if (tid < 64) {
            float v = (lgpart[0][tid] + lgpart[1][tid]) + (lgpart[2][tid] + lgpart[3][tid]);
            int t = t0 + tid;
            float m = mask[b * Ss + t];
            lg[t] = v + (1.0f - m) * (-3.402823466e38f);
        }
        __syncthreads();
    }

    float mx = -3.402823466e38f;
    for (int i = tid; i < Ss; i += 256) mx = fmaxf(mx, lg[i]);
#pragma unroll
    for (int o = 16; o; o >>= 1) mx = fmaxf(mx, __shfl_xor_sync(0xffffffffu, mx, o));
    if (lane == 0) red[warp] = mx;
    __syncthreads();
    mx = red[0];
#pragma unroll
    for (int w2i = 1; w2i < 8; ++w2i) mx = fmaxf(mx, red[w2i]);
    __syncthreads();

    float sum = 0.f;
    for (int i = tid; i < Ss; i += 256) {
        float e = __expf(lg[i] - mx);
        lg[i] = e;
        sum += e;
    }
#pragma unroll
    for (int o = 16; o; o >>= 1) sum += __shfl_xor_sync(0xffffffffu, sum, o);
    if (lane == 0) red[warp] = sum;
    __syncthreads();
    sum = 0.f;
#pragma unroll
    for (int w2i = 0; w2i < 8; ++w2i) sum += red[w2i];
    float inv = 1.0f / sum;

    float* orow = g_probs + (size_t)bs * Ss;
    for (int i = tid; i < Ss; i += 256) orow[i] = lg[i] * inv;
}

// ====== tf32 GEMM: 128x96 tile (R10), 2-slab-deep register prefetch pipeline ======
// MODE 0: ctx = probs @ H_i (per b); epilogue also writes ctxh = ctx * Hj
// MODE 1: hid = relu([ctx|Hj|ctxh] @ Wv1 + bv1)
// MODE 2: out = alpha * (hid @ Wv2 + bv2)
template <int MODE>
__global__ __launch_bounds__(256) void gemm_mma(const float* __restrict__ Ap,
                                                const float* __restrict__ Bp,
                                                const float* __restrict__ Hjp,
                                                const float* __restrict__ bias,
                                                const float* __restrict__ alpha,
                                                float* __restrict__ Cp, int Kdim, int lda) {
    const int m0 = blockIdx.x * 128;
    const int n0 = blockIdx.y * 96;
    const float* A = Ap;
    const float* Bm = Bp;
    float* C = Cp;
    size_t rowbase = 0;
    if (MODE == 0) {
        int b = blockIdx.z;
        A += (size_t)b * Ss * Ss;
        Bm += (size_t)b * Ss * Hh;
        C += (size_t)b * Ss * Hh;
        rowbase = (size_t)b * Ss;
    }

    __shared__ unsigned As[2][128][20];
    __shared__ unsigned Bs[2][16][104];

    const int tid  = threadIdx.x;
    const int warp = tid >> 5, lane = tid & 31;
    const int g  = lane >> 2, t4 = lane & 3;
    const int wm = warp & 3;
    const int wn = warp >> 2;

    const int ar = tid >> 1, ac = (tid & 1) * 8;
    const int b0r = tid / 24, b0c = (tid % 24) * 4;
    const int i1  = tid + 256;
    const int b1r = i1 / 24, b1c = (i1 % 24) * 4;
    const bool hasB1 = (tid < 128);

    float acc[2][6][4];
#pragma unroll
    for (int mt = 0; mt < 2; ++mt)
#pragma unroll
        for (int nt = 0; nt < 6; ++nt)
#pragma unroll
            for (int v = 0; v < 4; ++v) acc[mt][nt][v] = 0.f;

    const int nkt = Kdim / 16;   // 64 / 144 / 48 — always even

    auto loadABv = [&](float4& qa0, float4& qa1, float4& qb0, float4& qb1, int k0) {
        int kc = k0 + ac;
        if (MODE == 1) {
            int seg = kc / Hh;
            const float* base = (seg == 0) ? g_ctx : (seg == 1) ? Hjp : g_ctxh;
            int kq = kc - seg * Hh;
            qa0 = *(const float4*)(base + (size_t)(m0 + ar) * Hh + kq);
            qa1 = *(const float4*)(base + (size_t)(m0 + ar) * Hh + kq + 4);
        } else {
            qa0 = *(const float4*)(A + (size_t)(m0 + ar) * lda + kc);
            qa1 = *(const float4*)(A + (size_t)(m0 + ar) * lda + kc + 4);
        }
        qb0 = *(const float4*)(Bm + (size_t)(k0 + b0r) * Hh + n0 + b0c);
        if (hasB1) qb1 = *(const float4*)(Bm + (size_t)(k0 + b1r) * Hh + n0 + b1c);
    };

    auto storeABv = [&](const float4& qa0, const float4& qa1, const float4& qb0,
                        const float4& qb1, int buf) {
        const float va[8] = {qa0.x, qa0.y, qa0.z, qa0.w, qa1.x, qa1.y, qa1.z, qa1.w};
#pragma unroll
        for (int j = 0; j < 8; ++j) As[buf][ar][ac + j] = tf32r(va[j]);
        const float w0[4] = {qb0.x, qb0.y, qb0.z, qb0.w};
#pragma unroll
        for (int j = 0; j < 4; ++j) Bs[buf][b0r][b0c + j] = tf32r(w0[j]);
        if (hasB1) {
            const float w1[4] = {qb1.x, qb1.y, qb1.z, qb1.w};
#pragma unroll
            for (int j = 0; j < 4; ++j) Bs[buf][b1r][b1c + j] = tf32r(w1[j]);
        }
    };

    auto mmaStep = [&](int cur) {
#pragma unroll
        for (int k8 = 0; k8 < 16; k8 += 8) {
            unsigned afr[2][4], bfr[6][2];
#pragma unroll
            for (int mt = 0; mt < 2; ++mt) {
                int rb = wm * 32 + mt * 16 + g;
                afr[mt][0] = As[cur][rb][k8 + t4];
                afr[mt][1] = As[cur][rb + 8][k8 + t4];
                afr[mt][2] = As[cur][rb][k8 + t4 + 4];
                afr[mt][3] = As[cur][rb + 8][k8 + t4 + 4];
            }
#pragma unroll
            for (int nt = 0; nt < 6; ++nt) {
                int cb = wn * 48 + nt * 8 + g;
                bfr[nt][0] = Bs[cur][k8 + t4][cb];
                bfr[nt][1] = Bs[cur][k8 + t4 + 4][cb];
            }
#pragma unroll
            for (int mt = 0; mt < 2; ++mt)
#pragma unroll
                for (int nt = 0; nt < 6; ++nt)
                    mma_tf32(acc[mt][nt][0], acc[mt][nt][1], acc[mt][nt][2], acc[mt][nt][3],
                             afr[mt][0], afr[mt][1], afr[mt][2], afr[mt][3],
                             bfr[nt][0], bfr[nt][1]);
        }
    };

    // prologue: slab0 -> set0 -> buf0; slab1 -> set1 (stored at iter 0)
    float4 a0s0, a1s0, b0s0, b1s0;
    float4 a0s1, a1s1, b0s1, b1s1;
    loadABv(a0s0, a1s0, b0s0, b1s0, 0);
    loadABv(a0s1, a1s1, b0s1, b1s1, 16);
    storeABv(a0s0, a1s0, b0s0, b1s0, 0);
    __syncthreads();

#pragma unroll 1
    for (int kt = 0; kt < nkt; kt += 2) {
        // even slab kt: mma buf0
        if (kt + 1 < nkt) storeABv(a0s1, a1s1, b0s1, b1s1, 1);       // slab kt+1 -> buf1
        if (kt + 2 < nkt) loadABv(a0s0, a1s0, b0s0, b1s0, (kt + 2) * 16);  // slab kt+2 -> set0
        mmaStep(0);
        if (kt + 1 < nkt) __syncthreads();
        // odd slab kt+1: mma buf1
        if (kt + 1 < nkt) {
            if (kt + 2 < nkt) storeABv(a0s0, a1s0, b0s0, b1s0, 0);   // slab kt+2 -> buf0
            if (kt + 3 < nkt) loadABv(a0s1, a1s1, b0s1, b1s1, (kt + 3) * 16);  // slab kt+3 -> set1
            mmaStep(1);
            if (kt + 2 < nkt) __syncthreads();
        }
    }

    // ---------------- epilogue ----------------
    const float al = (MODE == 2) ? alpha[0] : 0.f;
#pragma unroll
    for (int mt = 0; mt < 2; ++mt) {
        int r0 = m0 + wm * 32 + mt * 16 + g;
        int r1 = r0 + 8;
#pragma unroll
        for (int nt = 0; nt < 6; ++nt) {
            int c0 = n0 + wn * 48 + nt * 8 + 2 * t4;
            float v00 = acc[mt][nt][0], v01 = acc[mt][nt][1];
            float v10 = acc[mt][nt][2], v11 = acc[mt][nt][3];
            if (MODE == 0) {
                *(float2*)(&C[(size_t)r0 * Hh + c0]) = make_float2(v00, v01);
                *(float2*)(&C[(size_t)r1 * Hh + c0]) = make_float2(v10, v11);
                size_t g0 = rowbase + r0, g1 = rowbase + r1;
                float2 h0 = *(const float2*)(Hjp + g0 * Hh + c0);
                float2 h1 = *(const float2*)(Hjp + g1 * Hh + c0);
                *(float2*)(&g_ctxh[g0 * Hh + c0]) = make_float2(v00 * h0.x, v01 * h0.y);
                *(float2*)(&g_ctxh[g1 * Hh + c0]) = make_float2(v10 * h1.x, v11 * h1.y);
            } else if (MODE == 1) {
                float2 bsv = *(const float2*)(&bias[c0]);
                *(float2*)(&C[(size_t)r0 * VHID + c0]) =
                    make_float2(fmaxf(v00 + bsv.x, 0.f), fmaxf(v01 + bsv.y, 0.f));
                *(float2*)(&C[(size_t)r1 * VHID + c0]) =
                    make_float2(fmaxf(v10 + bsv.x, 0.f), fmaxf(v11 + bsv.y, 0.f));
            } else {
                float2 bsv = *(const float2*)(&bias[c0]);
                *(float2*)(&C[(size_t)r0 * Hh + c0]) =
                    make_float2(al * (v00 + bsv.x), al * (v01 + bsv.y));
                *(float2*)(&C[(size_t)r1 * Hh + c0]) =
                    make_float2(al * (v10 + bsv.x), al * (v11 + bsv.y));
            }
        }
    }
}

// ================= launch =================
extern "C" void kernel_launch(void* const* d_in, const int* in_sizes, int n_in, void* d_out,
                              int out_size) {
    const float* Hj   = (const float*)d_in[0];
    const float* Hi   = (const float*)d_in[1];
    const float* mask = (const float*)d_in[2];
    const float* Wpj  = (const float*)d_in[3];
    const float* Wpi  = (const float*)d_in[4];
    const float* W1   = (const float*)d_in[5];
    const float* b1   = (const float*)d_in[6];
    const float* W2   = (const float*)d_in[7];
    // d_in[8] = b2: constant logit shift -> cancels in softmax
    const float* Wv1   = (const float*)d_in[9];
    const float* bv1   = (const float*)d_in[10];
    const float* Wv2   = (const float*)d_in[11];
    const float* bv2   = (const float*)d_in[12];
    const float* alpha = (const float*)d_in[13];
    float* out = (float*)d_out;

    float* d_probs = nullptr;
    float* d_ctx = nullptr;
    float* d_hid = nullptr;
    cudaGetSymbolAddress((void**)&d_probs, g_probs);
    cudaGetSymbolAddress((void**)&d_ctx, g_ctx);
    cudaGetSymbolAddress((void**)&d_hid, g_hid);

    k1_prep<<<Bb * Ss, 128>>>(Hj, Hi, Wpj, Wpi, W1, b1);
    k2_mma<<<Bb * Ss, 256>>>(W1, W2, mask);
    gemm_mma<0><<<dim3(Ss / 128, Hh / 96, Bb), 256>>>(d_probs, Hi, Hj, nullptr, nullptr,
                                                      d_ctx, Ss, Ss);
    gemm_mma<1><<<dim3(Bb * Ss / 128, VHID / 96), 256>>>(nullptr, Wv1, Hj, bv1, nullptr, d_hid,
                                                         VIN, 0);
    gemm_mma<2><<<dim3(Bb * Ss / 128, Hh / 96), 256>>>(d_hid, Wv2, nullptr, bv2, alpha, out,
                                                       VHID, VHID);
}